// round 8
// baseline (speedup 1.0000x reference)
#include <cuda_runtime.h>
#include <cuda_bf16.h>

typedef unsigned long long ull;

// scratch (device globals; allocations are forbidden)
__device__ ull g_k[64 * 64];                     // paired circ-conv kernels [cpair][8*8]
__device__ ull g_t[(size_t)8 * 32 * 256 * 256];  // paired intermediate [b][cpair][256][256]

__device__ __forceinline__ ull pk2(float a, float b) {
    ull r; asm("mov.b64 %0, {%1, %2};" : "=l"(r) : "f"(a), "f"(b)); return r;
}
__device__ __forceinline__ void fma2(ull &d, ull a, ull b) {
    asm("fma.rn.f32x2 %0, %1, %2, %0;" : "+l"(d) : "l"(a), "l"(b));
}
__device__ __forceinline__ float lo32(ull v) { return __int_as_float((int)(v & 0xffffffffull)); }
__device__ __forceinline__ float hi32(ull v) { return __int_as_float((int)(v >> 32)); }

// ---- kernel 1: build paired circular-conv kernels from fft_filt -------------
__global__ void k_build(const float* __restrict__ filt) {
    int cp = blockIdx.x, pix = threadIdx.x;
    int di = pix >> 3, dj = pix & 7;
    float v[2];
#pragma unroll
    for (int h = 0; h < 2; h++) {
        const float* F = filt + (cp * 2 + h) * 40;
        float s = 0.f;
        for (int ky = 0; ky < 8; ky++)
            for (int kx = 0; kx < 5; kx++) {
                float w = (kx == 0 || kx == 4) ? 1.f : 2.f;
                int m = (ky * di + kx * dj) & 7;
                s += w * F[ky * 5 + kx] * cospif(0.25f * (float)m);
            }
        v[h] = s * (1.f / 64.f);
    }
    g_k[cp * 64 + pix] = pk2(v[0], v[1]);
}

// ---- kernel 2: passA per 8x8 patch ------------------------------------------
#define NT 256
__global__ __launch_bounds__(256, 1) void passA(const float* __restrict__ x,
                                                const float* __restrict__ w_in,
                                                const float* __restrict__ w_before) {
    extern __shared__ char sm[];
    float* sWinT = (float*)sm;               // [128k][128o] 64KB
    float* sWbT  = (float*)(sm + 65536);     // [64k][64o]   16KB
    ull*   sK    = (ull*)(sm + 81920);       // [64cp][64]   32KB
    char*  bufA  = sm + 114688;              // 32KB
    char*  bufB  = sm + 147456;              // 32KB

    int tid = threadIdx.x;
    for (int idx = tid; idx < 16384; idx += NT) {
        int o = idx >> 7, k = idx & 127;
        sWinT[k * 128 + o] = w_in[idx];
    }
    for (int idx = tid; idx < 4096; idx += NT) {
        int o = idx >> 6, k = idx & 63;
        sWbT[k * 64 + o] = w_before[idx];
    }
    for (int idx = tid; idx < 4096; idx += NT) sK[idx] = g_k[idx];
    __syncthreads();

    const int to16 = tid & 15, tu16 = tid >> 4;
    const int to8  = tid & 7,  tu32 = tid >> 3;

    for (int pi = 0; pi < 8; ++pi) {
        int p = blockIdx.x * 8 + pi;
        int b = p >> 10, ph = (p >> 5) & 31, pw = p & 31;
        long basepix = ((long)b * 128) * 65536 + (long)(ph * 8) * 256 + pw * 8;

        // load x patch -> bufA as floats [c][64]
        {
            float4* dst = (float4*)bufA;
            for (int f = tid; f < 2048; f += NT) {
                int c = f >> 4, rem = f & 15, i = rem >> 1, q = rem & 1;
                dst[f] = *(const float4*)(x + basepix + (long)c * 65536 + i * 256 + q * 4);
            }
        }
        __syncthreads();

        // GEMM1: y pairs [64op][64px] -> bufB
        {
            const float* sX = (const float*)bufA;
            const ull* w64 = (const ull*)sWinT;
            ull acc[4][4];
#pragma unroll
            for (int i = 0; i < 4; i++)
#pragma unroll
                for (int j = 0; j < 4; j++) acc[i][j] = 0ull;
#pragma unroll 4
            for (int k = 0; k < 128; k++) {
                ulonglong2 A01 = *(const ulonglong2*)(w64 + k * 64 + to16 * 4);
                ulonglong2 A23 = *(const ulonglong2*)(w64 + k * 64 + to16 * 4 + 2);
                float4 bx = *(const float4*)(sX + k * 64 + tu16 * 4);
                ull A[4] = {A01.x, A01.y, A23.x, A23.y};
                ull Bp[4] = {pk2(bx.x, bx.x), pk2(bx.y, bx.y), pk2(bx.z, bx.z), pk2(bx.w, bx.w)};
#pragma unroll
                for (int i = 0; i < 4; i++)
#pragma unroll
                    for (int j = 0; j < 4; j++) fma2(acc[i][j], A[i], Bp[j]);
            }
            ull* sY = (ull*)bufB;
#pragma unroll
            for (int i = 0; i < 4; i++)
#pragma unroll
                for (int j = 0; j < 4; j++)
                    sY[(to16 * 4 + i) * 64 + tu16 * 4 + j] = acc[i][j];
        }
        __syncthreads();

        // circular conv 8x8 per channel pair: z -> bufA
        {
            const ull* sY = (const ull*)bufB;
            ull* sZ = (ull*)bufA;
            for (int un = 0; un < 2; ++un) {
                int unit = tid + un * 256;
                int cp = unit >> 3, ii = unit & 7;
                const ull* yb = sY + cp * 64;
                const ull* kb = sK + cp * 64;
                ull z[8];
#pragma unroll
                for (int j = 0; j < 8; j++) z[j] = 0ull;
#pragma unroll
                for (int a = 0; a < 8; a++) {
                    ulonglong2 y01 = *(const ulonglong2*)(yb + a * 8);
                    ulonglong2 y23 = *(const ulonglong2*)(yb + a * 8 + 2);
                    ulonglong2 y45 = *(const ulonglong2*)(yb + a * 8 + 4);
                    ulonglong2 y67 = *(const ulonglong2*)(yb + a * 8 + 6);
                    ull yv[8] = {y01.x, y01.y, y23.x, y23.y, y45.x, y45.y, y67.x, y67.y};
                    int r = (ii - a) & 7;
                    ulonglong2 k01 = *(const ulonglong2*)(kb + r * 8);
                    ulonglong2 k23 = *(const ulonglong2*)(kb + r * 8 + 2);
                    ulonglong2 k45 = *(const ulonglong2*)(kb + r * 8 + 4);
                    ulonglong2 k67 = *(const ulonglong2*)(kb + r * 8 + 6);
                    ull kv[8] = {k01.x, k01.y, k23.x, k23.y, k45.x, k45.y, k67.x, k67.y};
#pragma unroll
                    for (int j = 0; j < 8; j++)
#pragma unroll
                        for (int bb = 0; bb < 8; bb++)
                            fma2(z[j], yv[bb], kv[(j - bb) & 7]);
                }
#pragma unroll
                for (int j = 0; j < 8; j++) sZ[cp * 64 + ii * 8 + j] = z[j];
            }
        }
        __syncthreads();

        // exact GELU gate: g floats [64ch][64px] -> bufB[0..16K)
        {
            const float2* z2 = (const float2*)bufA;
            float* sG = (float*)bufB;
            for (int idx = tid; idx < 2048; idx += NT) {
                int cp = idx >> 6, u = idx & 63;
                float2 za = z2[cp * 64 + u];
                float2 zb = z2[(cp + 32) * 64 + u];
                sG[(2 * cp) * 64 + u] =
                    0.5f * za.x * (1.f + erff(za.x * 0.70710678118654752f)) * zb.x;
                sG[(2 * cp + 1) * 64 + u] =
                    0.5f * za.y * (1.f + erff(za.y * 0.70710678118654752f)) * zb.y;
            }
        }
        __syncthreads();

        // GEMM2: t pairs [32op][64px] -> bufB+16K
        {
            const float* sG = (const float*)bufB;
            const ull* wb64 = (const ull*)sWbT;
            ull acc[4][2];
#pragma unroll
            for (int i = 0; i < 4; i++) { acc[i][0] = 0ull; acc[i][1] = 0ull; }
#pragma unroll 4
            for (int k = 0; k < 64; k++) {
                ulonglong2 A01 = *(const ulonglong2*)(wb64 + k * 32 + to8 * 4);
                ulonglong2 A23 = *(const ulonglong2*)(wb64 + k * 32 + to8 * 4 + 2);
                float2 gg = *(const float2*)(sG + k * 64 + tu32 * 2);
                ull A[4] = {A01.x, A01.y, A23.x, A23.y};
                ull b0 = pk2(gg.x, gg.x), b1 = pk2(gg.y, gg.y);
#pragma unroll
                for (int i = 0; i < 4; i++) { fma2(acc[i][0], A[i], b0); fma2(acc[i][1], A[i], b1); }
            }
            ull* sT = (ull*)(bufB + 16384);
#pragma unroll
            for (int i = 0; i < 4; i++)
#pragma unroll
                for (int j = 0; j < 2; j++)
                    sT[(to8 * 4 + i) * 64 + tu32 * 2 + j] = acc[i][j];
        }
        __syncthreads();

        // store paired t to global
        {
            const ull* sT = (const ull*)(bufB + 16384);
            for (int idx = tid; idx < 2048; idx += NT) {
                int cp = idx >> 6, u = idx & 63, i = u >> 3, j = u & 7;
                g_t[((long)(b * 32 + cp) * 256 + ph * 8 + i) * 256 + pw * 8 + j] = sT[idx];
            }
        }
        __syncthreads();
    }
}

// ---- kernel 3: passB per 16x16 pixel tile ------------------------------------
__global__ __launch_bounds__(256, 1) void passB(const float* __restrict__ x,
                                                const float* __restrict__ wdw,
                                                const float* __restrict__ wout,
                                                float* __restrict__ outp) {
    extern __shared__ char sm[];
    float* sWoT = (float*)sm;              // [64k][128o] 32KB
    float* sDW  = (float*)(sm + 32768);    // 576 floats
    ull*   sT   = (ull*)(sm + 35072);      // [32cp][18][18]  82944B
    float* sD   = (float*)(sm + 118016);   // [64ch][256px]   64KB

    int tid = threadIdx.x, bx = blockIdx.x;
    int b = bx >> 8, tno = bx & 255;
    int ty = tno >> 4, tx = tno & 15;
    int y0 = ty * 16, x0g = tx * 16;

    for (int idx = tid; idx < 8192; idx += 256) {
        int o = idx >> 6, k = idx & 63;
        sWoT[k * 128 + o] = wout[idx];
    }
    for (int idx = tid; idx < 576; idx += 256) sDW[idx] = wdw[idx];
    for (int idx = tid; idx < 10368; idx += 256) {
        int cp = idx / 324, r = idx - cp * 324;
        int ly = r / 18, lx = r - ly * 18;
        int gy = y0 - 1 + ly, gx = x0g - 1 + lx;
        ull v = 0ull;
        if ((unsigned)gy < 256u && (unsigned)gx < 256u)
            v = g_t[((long)(b * 32 + cp) * 256 + gy) * 256 + gx];
        sT[idx] = v;
    }
    __syncthreads();

    // depthwise 3x3 (channel pairs) -> sD floats [ch][px]
    {
        int cp = tid >> 3, lx0 = (tid & 7) * 2;
        ull w9[9];
#pragma unroll
        for (int t = 0; t < 9; t++)
            w9[t] = pk2(sDW[(2 * cp) * 9 + t], sDW[(2 * cp + 1) * 9 + t]);
        const ull* base = sT + cp * 324;
        for (int oy = 0; oy < 16; ++oy) {
            ull a0 = 0ull, a1 = 0ull;
#pragma unroll
            for (int ki = 0; ki < 3; ki++) {
                const ull* row = base + (oy + ki) * 18 + lx0;
                ull r0 = row[0], r1 = row[1], r2 = row[2], r3 = row[3];
                fma2(a0, w9[ki * 3 + 0], r0);
                fma2(a0, w9[ki * 3 + 1], r1);
                fma2(a0, w9[ki * 3 + 2], r2);
                fma2(a1, w9[ki * 3 + 0], r1);
                fma2(a1, w9[ki * 3 + 1], r2);
                fma2(a1, w9[ki * 3 + 2], r3);
            }
            int px = oy * 16 + lx0;
            sD[(2 * cp) * 256 + px]         = lo32(a0);
            sD[(2 * cp + 1) * 256 + px]     = hi32(a0);
            sD[(2 * cp) * 256 + px + 1]     = lo32(a1);
            sD[(2 * cp + 1) * 256 + px + 1] = hi32(a1);
        }
    }
    __syncthreads();

    // GEMM3 (Wout) + residual + store
    {
        int to16 = tid & 15, tu16 = tid >> 4;
        const ull* wo64 = (const ull*)sWoT;
        for (int hx = 0; hx < 2; ++hx) {
            int pxb = tu16 * 16 + hx * 8;
            ull acc[4][8];
#pragma unroll
            for (int i = 0; i < 4; i++)
#pragma unroll
                for (int j = 0; j < 8; j++) acc[i][j] = 0ull;
#pragma unroll 4
            for (int k = 0; k < 64; k++) {
                ulonglong2 A01 = *(const ulonglong2*)(wo64 + k * 64 + to16 * 4);
                ulonglong2 A23 = *(const ulonglong2*)(wo64 + k * 64 + to16 * 4 + 2);
                float4 g0 = *(const float4*)(sD + k * 256 + pxb);
                float4 g1 = *(const float4*)(sD + k * 256 + pxb + 4);
                ull A[4] = {A01.x, A01.y, A23.x, A23.y};
                ull Bp[8] = {pk2(g0.x, g0.x), pk2(g0.y, g0.y), pk2(g0.z, g0.z), pk2(g0.w, g0.w),
                             pk2(g1.x, g1.x), pk2(g1.y, g1.y), pk2(g1.z, g1.z), pk2(g1.w, g1.w)};
#pragma unroll
                for (int i = 0; i < 4; i++)
#pragma unroll
                    for (int j = 0; j < 8; j++) fma2(acc[i][j], A[i], Bp[j]);
            }
            int gy = y0 + tu16, gx = x0g + hx * 8;
#pragma unroll
            for (int i = 0; i < 4; i++) {
                int ch0 = 2 * (to16 * 4 + i);
                long base0 = ((long)(b * 128 + ch0)) * 65536 + gy * 256 + gx;
                long base1 = base0 + 65536;
                float4 xa0 = *(const float4*)(x + base0);
                float4 xa1 = *(const float4*)(x + base0 + 4);
                float4 xb0 = *(const float4*)(x + base1);
                float4 xb1 = *(const float4*)(x + base1 + 4);
                float4 oa0, oa1, ob0, ob1;
                oa0.x = lo32(acc[i][0]) + xa0.x; ob0.x = hi32(acc[i][0]) + xb0.x;
                oa0.y = lo32(acc[i][1]) + xa0.y; ob0.y = hi32(acc[i][1]) + xb0.y;
                oa0.z = lo32(acc[i][2]) + xa0.z; ob0.z = hi32(acc[i][2]) + xb0.z;
                oa0.w = lo32(acc[i][3]) + xa0.w; ob0.w = hi32(acc[i][3]) + xb0.w;
                oa1.x = lo32(acc[i][4]) + xa1.x; ob1.x = hi32(acc[i][4]) + xb1.x;
                oa1.y = lo32(acc[i][5]) + xa1.y; ob1.y = hi32(acc[i][5]) + xb1.y;
                oa1.z = lo32(acc[i][6]) + xa1.z; ob1.z = hi32(acc[i][6]) + xb1.z;
                oa1.w = lo32(acc[i][7]) + xa1.w; ob1.w = hi32(acc[i][7]) + xb1.w;
                *(float4*)(outp + base0)     = oa0;
                *(float4*)(outp + base0 + 4) = oa1;
                *(float4*)(outp + base1)     = ob0;
                *(float4*)(outp + base1 + 4) = ob1;
            }
        }
    }
}

extern "C" void kernel_launch(void* const* d_in, const int* in_sizes, int n_in,
                              void* d_out, int out_size) {
    const float* x        = (const float*)d_in[0];
    const float* fft_filt = (const float*)d_in[1];
    const float* w_in     = (const float*)d_in[2];
    const float* w_before = (const float*)d_in[3];
    const float* w_dw     = (const float*)d_in[4];
    const float* w_out    = (const float*)d_in[5];
    float* outp = (float*)d_out;

    cudaFuncSetAttribute(passA, cudaFuncAttributeMaxDynamicSharedMemorySize, 180224);
    cudaFuncSetAttribute(passB, cudaFuncAttributeMaxDynamicSharedMemorySize, 183552);

    k_build<<<64, 64>>>(fft_filt);
    passA<<<1024, 256, 180224>>>(x, w_in, w_before);
    passB<<<2048, 256, 183552>>>(x, w_dw, w_out, outp);
}

// round 9
// speedup vs baseline: 1.4266x; 1.4266x over previous
#include <cuda_runtime.h>
#include <cuda_bf16.h>

typedef unsigned long long ull;

// scratch (device globals; allocations are forbidden)
__device__ ull g_k[64 * 64];                     // paired circ-conv kernels [cpair][8*8]
__device__ ull g_t[(size_t)8 * 32 * 256 * 256];  // paired intermediate [b][cpair][256][256]

__device__ __forceinline__ ull pk2(float a, float b) {
    ull r; asm("mov.b64 %0, {%1, %2};" : "=l"(r) : "f"(a), "f"(b)); return r;
}
__device__ __forceinline__ void fma2(ull &d, ull a, ull b) {
    asm("fma.rn.f32x2 %0, %1, %2, %0;" : "+l"(d) : "l"(a), "l"(b));
}
__device__ __forceinline__ float lo32(ull v) { return __int_as_float((int)(v & 0xffffffffull)); }
__device__ __forceinline__ float hi32(ull v) { return __int_as_float((int)(v >> 32)); }

// ---- kernel 1: build paired circular-conv kernels from fft_filt -------------
__global__ void k_build(const float* __restrict__ filt) {
    int cp = blockIdx.x, pix = threadIdx.x;
    int di = pix >> 3, dj = pix & 7;
    float v[2];
#pragma unroll
    for (int h = 0; h < 2; h++) {
        const float* F = filt + (cp * 2 + h) * 40;
        float s = 0.f;
        for (int ky = 0; ky < 8; ky++)
            for (int kx = 0; kx < 5; kx++) {
                float w = (kx == 0 || kx == 4) ? 1.f : 2.f;
                int m = (ky * di + kx * dj) & 7;
                s += w * F[ky * 5 + kx] * cospif(0.25f * (float)m);
            }
        v[h] = s * (1.f / 64.f);
    }
    g_k[cp * 64 + pix] = pk2(v[0], v[1]);
}

// ---- kernel 2: passA, 2 horizontally-adjacent 8x8 patches per iteration -----
// smem: sWin(paired)64K | sWb(paired)16K | bufA 68K | bufB 68K  = 221184 B
// strides: x rows 132 f, y/z/t rows 130 ull, g rows 132 f
__global__ __launch_bounds__(256, 1) void passA(const float* __restrict__ x,
                                                const float* __restrict__ w_in,
                                                const float* __restrict__ w_before) {
    extern __shared__ char sm[];
    ull*  sWin = (ull*)sm;                // [128k][64op]
    ull*  sWb  = (ull*)(sm + 65536);      // [64k][32op]
    char* bufA = sm + 81920;              // 69632 B
    char* bufB = sm + 151552;             // 69632 B
    int tid = threadIdx.x;

    // stage + pack weights (paired u64)
    {
        float* stA = (float*)bufA;
        float* stB = (float*)bufB;
        for (int i = tid; i < 16384; i += 256) stA[i] = w_in[i];
        for (int i = tid; i < 4096;  i += 256) stB[i] = w_before[i];
        __syncthreads();
        for (int i = tid; i < 8192; i += 256) {
            int k = i >> 6, op = i & 63;
            sWin[k * 64 + op] = pk2(stA[(2 * op) * 128 + k], stA[(2 * op + 1) * 128 + k]);
        }
        for (int i = tid; i < 2048; i += 256) {
            int k = i >> 5, op = i & 31;
            sWb[k * 32 + op] = pk2(stB[(2 * op) * 64 + k], stB[(2 * op + 1) * 64 + k]);
        }
        __syncthreads();
    }

    const int og  = tid & 15, pg  = tid >> 4;  // GEMM1: 4 opairs x 8 px
    const int cc  = tid >> 2, sub = tid & 3;   // circconv: cp x (ii in {sub,sub+4}) x 2 patches
    const int og2 = tid & 7,  pg2 = tid >> 3;  // GEMM2 (tid<128)

    for (int q = 0; q < 4; ++q) {
        int p2 = blockIdx.x * 4 + q;                       // 0..4095 patch pairs
        int b = p2 >> 9, rem = p2 & 511;
        int ph = rem >> 4, pw0 = (rem & 15) << 1;
        const float* xb = x + ((long)b << 23) + (ph << 11) + (pw0 << 3);

        // load x: [128c][132f] in bufA, px = pc*64 + i*8 + j
        {
            float* sX = (float*)bufA;
            for (int f = tid; f < 4096; f += 256) {
                int c = f >> 5, r = f & 31, i = r >> 2, qq = r & 3;
                float4 v = *(const float4*)(xb + ((long)c << 16) + (i << 8) + (qq << 2));
                int px = (qq < 2) ? (i * 8 + qq * 4) : (64 + i * 8 + (qq - 2) * 4);
                *(float4*)(sX + c * 132 + px) = v;
            }
        }
        __syncthreads();

        // GEMM1: y[op][128px] paired -> bufB
        {
            const float* sX = (const float*)bufA;
            ull acc[4][8];
#pragma unroll
            for (int i = 0; i < 4; i++)
#pragma unroll
                for (int j = 0; j < 8; j++) acc[i][j] = 0ull;
#pragma unroll 4
            for (int k = 0; k < 128; k++) {
                const ull* Ar = sWin + k * 64 + og;
                ull A0 = Ar[0], A1 = Ar[16], A2 = Ar[32], A3 = Ar[48];
                const float* Br = sX + k * 132 + pg * 8;
                float4 b0 = *(const float4*)Br, b1 = *(const float4*)(Br + 4);
                ull B[8] = {pk2(b0.x, b0.x), pk2(b0.y, b0.y), pk2(b0.z, b0.z), pk2(b0.w, b0.w),
                            pk2(b1.x, b1.x), pk2(b1.y, b1.y), pk2(b1.z, b1.z), pk2(b1.w, b1.w)};
#pragma unroll
                for (int j = 0; j < 8; j++) {
                    fma2(acc[0][j], A0, B[j]); fma2(acc[1][j], A1, B[j]);
                    fma2(acc[2][j], A2, B[j]); fma2(acc[3][j], A3, B[j]);
                }
            }
            ull* sY = (ull*)bufB;
#pragma unroll
            for (int i = 0; i < 4; i++) {
                ull* dst = sY + (og + 16 * i) * 130 + pg * 8;
#pragma unroll
                for (int j = 0; j < 8; j += 2) {
                    ulonglong2 v; v.x = acc[i][j]; v.y = acc[i][j + 1];
                    *(ulonglong2*)(dst + j) = v;
                }
            }
        }
        __syncthreads();

        // circular conv 8x8 (K from global L2): z -> bufA
        {
            const ull* sY = (const ull*)bufB;
            ull* sZ = (ull*)bufA;
            const ull* kbase = g_k + cc * 64;
            ull z0[8], z1[8], z2[8], z3[8];
#pragma unroll
            for (int j = 0; j < 8; j++) { z0[j] = 0; z1[j] = 0; z2[j] = 0; z3[j] = 0; }
#pragma unroll 2
            for (int a = 0; a < 8; a++) {
                const ull* yr = sY + cc * 130 + a * 8;
                ull ya[8], yb[8];
#pragma unroll
                for (int j = 0; j < 8; j += 2) {
                    ulonglong2 v0 = *(const ulonglong2*)(yr + j);      ya[j] = v0.x; ya[j + 1] = v0.y;
                    ulonglong2 v1 = *(const ulonglong2*)(yr + 64 + j); yb[j] = v1.x; yb[j + 1] = v1.y;
                }
                int r1 = (sub - a) & 7, r2 = (sub + 4 - a) & 7;
                ull k1[8], k2[8];
#pragma unroll
                for (int j = 0; j < 8; j += 2) {
                    ulonglong2 u1 = *(const ulonglong2*)(kbase + r1 * 8 + j); k1[j] = u1.x; k1[j + 1] = u1.y;
                    ulonglong2 u2 = *(const ulonglong2*)(kbase + r2 * 8 + j); k2[j] = u2.x; k2[j + 1] = u2.y;
                }
#pragma unroll
                for (int j = 0; j < 8; j++)
#pragma unroll
                    for (int bb = 0; bb < 8; bb++) {
                        int r = (j - bb) & 7;
                        fma2(z0[j], ya[bb], k1[r]);
                        fma2(z1[j], yb[bb], k1[r]);
                        fma2(z2[j], ya[bb], k2[r]);
                        fma2(z3[j], yb[bb], k2[r]);
                    }
            }
            ull* zr = sZ + cc * 130;
#pragma unroll
            for (int j = 0; j < 8; j += 2) {
                ulonglong2 v;
                v.x = z0[j]; v.y = z0[j + 1]; *(ulonglong2*)(zr + sub * 8 + j) = v;
                v.x = z1[j]; v.y = z1[j + 1]; *(ulonglong2*)(zr + 64 + sub * 8 + j) = v;
                v.x = z2[j]; v.y = z2[j + 1]; *(ulonglong2*)(zr + (sub + 4) * 8 + j) = v;
                v.x = z3[j]; v.y = z3[j + 1]; *(ulonglong2*)(zr + 64 + (sub + 4) * 8 + j) = v;
            }
        }
        __syncthreads();

        // exact GELU gate: g floats [64ch][132] -> bufB
        {
            const ull* sZ = (const ull*)bufA;
            float* sG = (float*)bufB;
            for (int idx = tid; idx < 4096; idx += 256) {
                int cp = idx >> 7, u = idx & 127;
                ull za = sZ[cp * 130 + u], zb = sZ[(cp + 32) * 130 + u];
                float a0 = lo32(za), a1 = hi32(za);
                sG[(2 * cp) * 132 + u] =
                    0.5f * a0 * (1.f + erff(a0 * 0.70710678118654752f)) * lo32(zb);
                sG[(2 * cp + 1) * 132 + u] =
                    0.5f * a1 * (1.f + erff(a1 * 0.70710678118654752f)) * hi32(zb);
            }
        }
        __syncthreads();

        // GEMM2: t[32op][128px] paired -> bufB+33792
        if (tid < 128) {
            const float* sG = (const float*)bufB;
            ull acc[4][8];
#pragma unroll
            for (int i = 0; i < 4; i++)
#pragma unroll
                for (int j = 0; j < 8; j++) acc[i][j] = 0ull;
#pragma unroll 4
            for (int k = 0; k < 64; k++) {
                const ull* Ar = sWb + k * 32 + og2;
                ull A0 = Ar[0], A1 = Ar[8], A2 = Ar[16], A3 = Ar[24];
                const float* Br = sG + k * 132 + pg2 * 8;
                float4 b0 = *(const float4*)Br, b1 = *(const float4*)(Br + 4);
                ull B[8] = {pk2(b0.x, b0.x), pk2(b0.y, b0.y), pk2(b0.z, b0.z), pk2(b0.w, b0.w),
                            pk2(b1.x, b1.x), pk2(b1.y, b1.y), pk2(b1.z, b1.z), pk2(b1.w, b1.w)};
#pragma unroll
                for (int j = 0; j < 8; j++) {
                    fma2(acc[0][j], A0, B[j]); fma2(acc[1][j], A1, B[j]);
                    fma2(acc[2][j], A2, B[j]); fma2(acc[3][j], A3, B[j]);
                }
            }
            ull* sT = (ull*)(bufB + 33792);
#pragma unroll
            for (int i = 0; i < 4; i++) {
                ull* dst = sT + (og2 + 8 * i) * 130 + pg2 * 8;
#pragma unroll
                for (int j = 0; j < 8; j += 2) {
                    ulonglong2 v; v.x = acc[i][j]; v.y = acc[i][j + 1];
                    *(ulonglong2*)(dst + j) = v;
                }
            }
        }
        __syncthreads();

        // store paired t to global (128B-contiguous across the 2 patches)
        {
            const ull* sT = (const ull*)(bufB + 33792);
            for (int idx = tid; idx < 4096; idx += 256) {
                int cp = idx >> 7, r = idx & 127, i = r >> 4, w = r & 15;
                int pc = w >> 3, j = w & 7;
                ull v = sT[cp * 130 + pc * 64 + i * 8 + j];
                g_t[(((long)(b * 32 + cp)) << 16) + ((ph * 8 + i) << 8) + pw0 * 8 + pc * 8 + j] = v;
            }
        }
        __syncthreads();
    }
}

// ---- kernel 3: passB per 16x16 pixel tile, 512 threads ----------------------
__global__ __launch_bounds__(512, 1) void passB(const float* __restrict__ x,
                                                const float* __restrict__ wdw,
                                                const float* __restrict__ wout,
                                                float* __restrict__ outp) {
    extern __shared__ char sm[];
    ull*   sWo = (ull*)sm;              // [64k][64op] paired 32KB
    float* sDW = (float*)(sm + 32768);  // 576 floats
    ull*   sT  = (ull*)(sm + 35072);    // [32cp][18][18]  82944B
    float* sD  = (float*)(sm + 118016); // [64ch][256px]   64KB

    int tid = threadIdx.x, bx = blockIdx.x;
    int b = bx >> 8, tno = bx & 255;
    int ty = tno >> 4, tx = tno & 15;
    int y0 = ty * 16, x0g = tx * 16;

    // stage wout into sD, pack paired into sWo
    {
        float* st = sD;
        for (int i = tid; i < 8192; i += 512) st[i] = wout[i];
        __syncthreads();
        for (int i = tid; i < 4096; i += 512) {
            int k = i >> 6, op = i & 63;
            sWo[k * 64 + op] = pk2(st[(2 * op) * 64 + k], st[(2 * op + 1) * 64 + k]);
        }
    }
    for (int i = tid; i < 576; i += 512) sDW[i] = wdw[i];
    for (int idx = tid; idx < 10368; idx += 512) {
        int cp = idx / 324, r = idx - cp * 324;
        int ly = r / 18, lx = r - ly * 18;
        int gy = y0 - 1 + ly, gx = x0g - 1 + lx;
        ull v = 0ull;
        if ((unsigned)gy < 256u && (unsigned)gx < 256u)
            v = g_t[(((long)(b * 32 + cp)) << 16) + (gy << 8) + gx];
        sT[idx] = v;
    }
    __syncthreads();

    // depthwise 3x3 (channel pairs) -> sD floats [ch][px]
    {
        int cp = tid >> 4, s = tid & 15, lx0 = (s & 7) * 2, oy0 = (s >> 3) * 8;
        ull w9[9];
#pragma unroll
        for (int t = 0; t < 9; t++)
            w9[t] = pk2(sDW[(2 * cp) * 9 + t], sDW[(2 * cp + 1) * 9 + t]);
        const ull* base = sT + cp * 324;
        for (int oy = oy0; oy < oy0 + 8; ++oy) {
            ull a0 = 0ull, a1 = 0ull;
#pragma unroll
            for (int ki = 0; ki < 3; ki++) {
                const ull* row = base + (oy + ki) * 18 + lx0;
                ull r0 = row[0], r1 = row[1], r2 = row[2], r3 = row[3];
                fma2(a0, w9[ki * 3 + 0], r0);
                fma2(a0, w9[ki * 3 + 1], r1);
                fma2(a0, w9[ki * 3 + 2], r2);
                fma2(a1, w9[ki * 3 + 0], r1);
                fma2(a1, w9[ki * 3 + 1], r2);
                fma2(a1, w9[ki * 3 + 2], r3);
            }
            int px = oy * 16 + lx0;
            sD[(2 * cp) * 256 + px]         = lo32(a0);
            sD[(2 * cp + 1) * 256 + px]     = hi32(a0);
            sD[(2 * cp) * 256 + px + 1]     = lo32(a1);
            sD[(2 * cp + 1) * 256 + px + 1] = hi32(a1);
        }
    }
    __syncthreads();

    // GEMM3 (Wout paired) + residual + store
    {
        int og3 = tid & 15, pg3 = tid >> 4;  // 16 x 32 : 4 opairs x 8 px
        ull acc[4][8];
#pragma unroll
        for (int i = 0; i < 4; i++)
#pragma unroll
            for (int j = 0; j < 8; j++) acc[i][j] = 0ull;
#pragma unroll 4
        for (int k = 0; k < 64; k++) {
            const ull* Ar = sWo + k * 64 + og3;
            ull A0 = Ar[0], A1 = Ar[16], A2 = Ar[32], A3 = Ar[48];
            const float* Br = sD + k * 256 + pg3 * 8;
            float4 b0 = *(const float4*)Br, b1 = *(const float4*)(Br + 4);
            ull B[8] = {pk2(b0.x, b0.x), pk2(b0.y, b0.y), pk2(b0.z, b0.z), pk2(b0.w, b0.w),
                        pk2(b1.x, b1.x), pk2(b1.y, b1.y), pk2(b1.z, b1.z), pk2(b1.w, b1.w)};
#pragma unroll
            for (int j = 0; j < 8; j++) {
                fma2(acc[0][j], A0, B[j]); fma2(acc[1][j], A1, B[j]);
                fma2(acc[2][j], A2, B[j]); fma2(acc[3][j], A3, B[j]);
            }
        }
        int oy = pg3 >> 1, lxb = (pg3 & 1) * 8;
        int gy = y0 + oy, gx = x0g + lxb;
#pragma unroll
        for (int i = 0; i < 4; i++) {
            int ch0 = 2 * (og3 + 16 * i);
            long base0 = (((long)(b * 128 + ch0)) << 16) + (gy << 8) + gx;
            long base1 = base0 + 65536;
            float4 xa0 = *(const float4*)(x + base0), xa1 = *(const float4*)(x + base0 + 4);
            float4 xb0 = *(const float4*)(x + base1), xb1 = *(const float4*)(x + base1 + 4);
            float4 oa0, oa1, ob0, ob1;
            oa0.x = lo32(acc[i][0]) + xa0.x; ob0.x = hi32(acc[i][0]) + xb0.x;
            oa0.y = lo32(acc[i][1]) + xa0.y; ob0.y = hi32(acc[i][1]) + xb0.y;
            oa0.z = lo32(acc[i][2]) + xa0.z; ob0.z = hi32(acc[i][2]) + xb0.z;
            oa0.w = lo32(acc[i][3]) + xa0.w; ob0.w = hi32(acc[i][3]) + xb0.w;
            oa1.x = lo32(acc[i][4]) + xa1.x; ob1.x = hi32(acc[i][4]) + xb1.x;
            oa1.y = lo32(acc[i][5]) + xa1.y; ob1.y = hi32(acc[i][5]) + xb1.y;
            oa1.z = lo32(acc[i][6]) + xa1.z; ob1.z = hi32(acc[i][6]) + xb1.z;
            oa1.w = lo32(acc[i][7]) + xa1.w; ob1.w = hi32(acc[i][7]) + xb1.w;
            *(float4*)(outp + base0)     = oa0;
            *(float4*)(outp + base0 + 4) = oa1;
            *(float4*)(outp + base1)     = ob0;
            *(float4*)(outp + base1 + 4) = ob1;
        }
    }
}

extern "C" void kernel_launch(void* const* d_in, const int* in_sizes, int n_in,
                              void* d_out, int out_size) {
    const float* x        = (const float*)d_in[0];
    const float* fft_filt = (const float*)d_in[1];
    const float* w_in     = (const float*)d_in[2];
    const float* w_before = (const float*)d_in[3];
    const float* w_dw     = (const float*)d_in[4];
    const float* w_out    = (const float*)d_in[5];
    float* outp = (float*)d_out;

    cudaFuncSetAttribute(passA, cudaFuncAttributeMaxDynamicSharedMemorySize, 221184);
    cudaFuncSetAttribute(passB, cudaFuncAttributeMaxDynamicSharedMemorySize, 183552);

    k_build<<<64, 64>>>(fft_filt);
    passA<<<1024, 256, 221184>>>(x, w_in, w_before);
    passB<<<2048, 512, 183552>>>(x, w_dw, w_out, outp);
}